// round 2
// baseline (speedup 1.0000x reference)
#include <cuda_runtime.h>
#include <cstdint>

// ---------------- problem constants ----------------
#define N_TOK 4096
#define IN_F  4096
#define OUT_F 4096
#define N_BLK 8192
#define IN_B  128          // IN_FEATURES / 32
#define NBR   8            // block-rows per CTA -> 256 output cols
#define GCOLS 256
#define MT    128          // token tile

// ---------------- smem layout (dynamic) ----------------
#define OFF_NU     0
#define OFF_ROWOFF 32       // 9 ints
#define OFF_CNT    128      // 128 ints
#define OFF_UBC    640      // 128 u32
#define OFF_BIAS   1152     // 256 floats
#define OFF_ENT    2176     // up to 1024 u32
#define OFF_X      6400     // 2 x 18432B x-tile stages (128 rows, stride 36 floats)
#define X_STAGE    18432
#define OFF_W      43264    // 2 x 36864B weight stages (8 blocks * 4608B)
#define W_STAGE    36864
#define SMEM_TOTAL 116992

// tf32(round-to-nearest) copy of weight_data (alloc-free rule -> device global)
__device__ float g_wc[(size_t)N_BLK * 1024];

// ---------------- helpers ----------------
static __device__ __forceinline__ uint32_t smem_u32(const void* p) {
    uint32_t a;
    asm("{ .reg .u64 t; cvta.to.shared.u64 t, %1; cvt.u32.u64 %0, t; }" : "=r"(a) : "l"(p));
    return a;
}

static __device__ __forceinline__ void cp16(uint32_t dst, const void* src) {
    asm volatile("cp.async.cg.shared.global [%0], [%1], 16;" :: "r"(dst), "l"(src));
}
#define CP_COMMIT() asm volatile("cp.async.commit_group;" ::: "memory")
#define CP_WAIT(n)  asm volatile("cp.async.wait_group %0;" :: "n"(n) : "memory")

static __device__ __forceinline__ uint32_t f2tf32(float v) {
    uint32_t r;
    asm("cvt.rna.tf32.f32 %0, %1;" : "=r"(r) : "f"(v));
    return r;
}

static __device__ __forceinline__ void mma8(float (&d)[4], const uint32_t (&a)[4],
                                            const uint32_t (&b)[2]) {
    asm volatile(
        "mma.sync.aligned.m16n8k8.row.col.f32.tf32.tf32.f32 "
        "{%0,%1,%2,%3}, {%4,%5,%6,%7}, {%8,%9}, {%0,%1,%2,%3};"
        : "+f"(d[0]), "+f"(d[1]), "+f"(d[2]), "+f"(d[3])
        : "r"(a[0]), "r"(a[1]), "r"(a[2]), "r"(a[3]), "r"(b[0]), "r"(b[1]));
}

static __device__ __forceinline__ int lb(const int* __restrict__ a, int n, int v) {
    int lo = 0, hi = n;
    while (lo < hi) { int m = (lo + hi) >> 1; if (a[m] < v) lo = m + 1; else hi = m; }
    return lo;
}

// One 32x32 weight block against the warp's 32-token A fragments.
// J = block-row position within this warp's 4-block-row half (compile-time so
// accumulator indexing stays register-resident).
template<int J>
static __device__ __forceinline__ void do_block(float (&acc)[2][16][4],
                                                const uint32_t (&A)[4][2][4],
                                                const float* __restrict__ wb,
                                                int g, int t4) {
    #pragma unroll
    for (int ks = 0; ks < 4; ks++) {
        uint32_t B[4][2];
        #pragma unroll
        for (int nt = 0; nt < 4; nt++) {
            int n = nt * 8 + g;
            int k = ks * 8 + t4;
            B[nt][0] = __float_as_uint(wb[n * 36 + k]);
            B[nt][1] = __float_as_uint(wb[n * 36 + k + 4]);
        }
        #pragma unroll
        for (int mt = 0; mt < 2; mt++)
            #pragma unroll
            for (int nt = 0; nt < 4; nt++)
                mma8(acc[mt][J * 4 + nt], A[ks][mt], B[nt]);
    }
}

// ---------------- pre-pass: fp32 -> tf32(rna) bits for weights ----------------
__global__ void cvt_tf32_kernel(const float4* __restrict__ src, float4* __restrict__ dst, int n4) {
    for (int i = blockIdx.x * blockDim.x + threadIdx.x; i < n4; i += gridDim.x * blockDim.x) {
        float4 v = src[i];
        float4 o;
        o.x = __uint_as_float(f2tf32(v.x));
        o.y = __uint_as_float(f2tf32(v.y));
        o.z = __uint_as_float(f2tf32(v.z));
        o.w = __uint_as_float(f2tf32(v.w));
        dst[i] = o;
    }
}

// ---------------- main block-sparse GEMM ----------------
__global__ void __launch_bounds__(256, 1)
bsl_main(const float* __restrict__ x,
         const float* __restrict__ bias,
         const int* __restrict__ block_ids,
         float* __restrict__ out)
{
    extern __shared__ __align__(1024) char smem[];
    const uint32_t sb = smem_u32(smem);
    const int tid  = threadIdx.x;
    const int wid  = tid >> 5;
    const int lane = tid & 31;
    const int g    = lane >> 2;       // group id (0..7)
    const int t4   = lane & 3;        // thread-in-group
    const int wsub = wid & 3;         // token subtile (32 rows each)
    const int h    = wid >> 2;        // block-row half (4 block-rows each)
    const int m0   = blockIdx.x * MT;
    const int brg  = blockIdx.y;      // 8-block-row group (0..15)

    int*      row_off = (int*)(smem + OFF_ROWOFF);
    int*      cnt     = (int*)(smem + OFF_CNT);
    uint32_t* ubc     = (uint32_t*)(smem + OFF_UBC);
    float*    bias_s  = (float*)(smem + OFF_BIAS);
    uint32_t* ents    = (uint32_t*)(smem + OFF_ENT);

    // ---- planning: CSR row offsets for our 8 block-rows ----
    if (tid < 9) row_off[tid] = lb(block_ids, N_BLK, (brg * NBR + tid) * IN_B);
    if (tid >= 32 && tid < 160) cnt[tid - 32] = 0;
    if (tid < 256 && tid < GCOLS) bias_s[tid] = bias[brg * GCOLS + tid];
    __syncthreads();

    const int e0  = row_off[0];
    const int tot = row_off[NBR] - e0;

    for (int t = tid; t < tot; t += 256)
        atomicAdd(&cnt[block_ids[e0 + t] & 127], 1);
    __syncthreads();

    if (tid == 0) {
        int acc = 0, nuv = 0;
        for (int c = 0; c < 128; c++) {
            int cc = cnt[c];
            if (cc) ubc[nuv++] = ((uint32_t)c << 17) | ((uint32_t)acc << 5) | (uint32_t)cc;
            cnt[c] = acc; acc += cc;
        }
        *(int*)(smem + OFF_NU) = nuv;
    }
    __syncthreads();

    for (int t = tid; t < tot; t += 256) {
        int flat = block_ids[e0 + t];
        int bc   = flat & 127;
        int brl  = (flat >> 7) - brg * NBR;          // 0..7
        int pos  = atomicAdd(&cnt[bc], 1);
        ents[pos] = ((uint32_t)(e0 + t) << 8) | (uint32_t)brl;
    }
    __syncthreads();

    const int nu = *(int*)(smem + OFF_NU);

    // ---- loader (CTA-wide): x tile + weight blocks for one bc ----
    auto issue_loads = [&](int it, int stage) {
        uint32_t u = ubc[it];
        int bc = (int)(u >> 17);
        int st = (int)((u >> 5) & 0xFFF);
        int cc = (int)(u & 31);
        uint32_t xbase = sb + OFF_X + stage * X_STAGE;
        #pragma unroll
        for (int q = 0; q < 4; q++) {               // 1024 chunks / 256 thr
            int t = tid + q * 256;
            int r = t >> 3, c = t & 7;
            const float* src = x + (size_t)(m0 + r) * IN_F + bc * 32 + c * 4;
            cp16(xbase + (uint32_t)(r * 144 + c * 16), src);
        }
        uint32_t wbase = sb + OFF_W + stage * W_STAGE;
        int totc = cc << 8;                          // 256 chunks per block
        for (int t = tid; t < totc; t += 256) {
            int e = t >> 8, o = t & 255, r = o >> 3, c = o & 7;
            uint32_t gg = ents[st + e] >> 8;
            const float* src = g_wc + (size_t)gg * 1024 + r * 32 + c * 4;
            cp16(wbase + (uint32_t)(e * 4608 + r * 144 + c * 16), src);
        }
        CP_COMMIT();
    };

    float acc[2][16][4];
    #pragma unroll
    for (int mt = 0; mt < 2; mt++)
        #pragma unroll
        for (int nt = 0; nt < 16; nt++)
            #pragma unroll
            for (int q = 0; q < 4; q++) acc[mt][nt][q] = 0.0f;

    if (nu > 0) {
        issue_loads(0, 0);

        for (int i = 0; i < nu; i++) {
            int s = i & 1;
            if (i + 1 < nu) { issue_loads(i + 1, s ^ 1); CP_WAIT(1); }
            else            { CP_WAIT(0); }
            __syncthreads();

            uint32_t u = ubc[i];
            int st = (int)((u >> 5) & 0xFFF);
            int cc = (int)(u & 31);

            // does this warp's half have any block this iteration?
            bool any = false;
            for (int e = 0; e < cc; e++)
                if ((int)((ents[st + e] & 7) >> 2) == h) { any = true; break; }

            if (any) {
                const float* xs = (const float*)(smem + OFF_X + s * X_STAGE);
                const float* ws = (const float*)(smem + OFF_W + s * W_STAGE);

                // A fragments for this warp's 32 tokens (shared by all blocks of this bc)
                uint32_t A[4][2][4];
                #pragma unroll
                for (int ks = 0; ks < 4; ks++)
                    #pragma unroll
                    for (int mt = 0; mt < 2; mt++) {
                        const float* xr = xs + (wsub * 32 + mt * 16 + g) * 36 + ks * 8 + t4;
                        A[ks][mt][0] = f2tf32(xr[0]);
                        A[ks][mt][1] = f2tf32(xr[8 * 36]);
                        A[ks][mt][2] = f2tf32(xr[4]);
                        A[ks][mt][3] = f2tf32(xr[8 * 36 + 4]);
                    }

                for (int e = 0; e < cc; e++) {
                    uint32_t en = ents[st + e];
                    int brl = (int)(en & 7);
                    if ((brl >> 2) != h) continue;
                    const float* wb = ws + e * 1152;
                    switch (brl & 3) {
                        case 0: do_block<0>(acc, A, wb, g, t4); break;
                        case 1: do_block<1>(acc, A, wb, g, t4); break;
                        case 2: do_block<2>(acc, A, wb, g, t4); break;
                        default: do_block<3>(acc, A, wb, g, t4); break;
                    }
                }
            }
            __syncthreads();
        }
    }

    // ---- epilogue: registers -> gmem with bias ----
    {
        const float* bs = bias_s + h * 128;
        int rowb = m0 + wsub * 32 + g;
        #pragma unroll
        for (int mt = 0; mt < 2; mt++) {
            #pragma unroll
            for (int nt = 0; nt < 16; nt++) {
                int lc = nt * 8 + t4 * 2;
                float b0 = bs[lc], b1 = bs[lc + 1];
                int col = brg * GCOLS + h * 128 + lc;
                float* p0 = out + (size_t)(rowb + mt * 16) * OUT_F + col;
                float2 v0 = { acc[mt][nt][0] + b0, acc[mt][nt][1] + b1 };
                float2 v1 = { acc[mt][nt][2] + b0, acc[mt][nt][3] + b1 };
                *(float2*)p0 = v0;
                *(float2*)(p0 + 8 * OUT_F) = v1;
            }
        }
    }
}

// ---------------- launch ----------------
extern "C" void kernel_launch(void* const* d_in, const int* in_sizes, int n_in,
                              void* d_out, int out_size)
{
    const float* x    = (const float*)d_in[0];   // [4096,4096] f32
    const float* w    = (const float*)d_in[1];   // [8192,32,32] f32
    const float* bias = (const float*)d_in[2];   // [4096] f32
    const int*   bids = (const int*)d_in[3];     // [8192] i32 sorted flat ids
    float* out = (float*)d_out;

    void* pw = nullptr;
    cudaGetSymbolAddress(&pw, g_wc);

    cvt_tf32_kernel<<<2048, 256>>>((const float4*)w, (float4*)pw, (N_BLK * 1024) / 4);

    cudaFuncSetAttribute(bsl_main, cudaFuncAttributeMaxDynamicSharedMemorySize, SMEM_TOTAL);
    bsl_main<<<dim3(32, 16), 256, SMEM_TOTAL>>>(x, bias, bids, out);

    (void)in_sizes; (void)n_in; (void)out_size;
}

// round 3
// speedup vs baseline: 1.4235x; 1.4235x over previous
#include <cuda_runtime.h>
#include <cuda_fp16.h>
#include <cstdint>

// ---------------- problem constants ----------------
#define N_TOK 4096
#define IN_F  4096
#define OUT_F 4096
#define N_BLK 8192
#define IN_B  128          // IN_FEATURES / 32
#define NBR   8            // block-rows per CTA -> 256 output cols
#define GCOLS 256
#define MT    128          // token tile

// ---------------- smem layout (bytes) ----------------
#define OFF_NU     0
#define OFF_ROWOFF 32       // 9 ints
#define OFF_CNT    128      // 128 ints
#define OFF_UBC    640      // 128 u32
#define OFF_BIAS   1152     // 256 floats
#define OFF_ENT    2176     // up to 1024 u32
#define OFF_STG    6400     // 3 pipeline stages
#define X_SZ       10240    // 128 rows * 80B (32 halves + 16B pad)
#define WBLK       2560     // 32 rows * 80B
#define W_SZ       20480    // 8 blocks max
#define STAGE      30720
#define SMEM_TOTAL (6400 + 3 * STAGE)   // 98560

// fp16 copies of x and weights (alloc-free rule -> device globals)
__device__ __half g_xh[(size_t)N_TOK * IN_F];
__device__ __half g_wh[(size_t)N_BLK * 1024];

// ---------------- helpers ----------------
static __device__ __forceinline__ uint32_t smem_u32(const void* p) {
    uint32_t a;
    asm("{ .reg .u64 t; cvta.to.shared.u64 t, %1; cvt.u32.u64 %0, t; }" : "=r"(a) : "l"(p));
    return a;
}
static __device__ __forceinline__ void cp16(uint32_t dst, const void* src) {
    asm volatile("cp.async.cg.shared.global [%0], [%1], 16;" :: "r"(dst), "l"(src));
}
#define CP_COMMIT() asm volatile("cp.async.commit_group;" ::: "memory")
#define CP_WAIT(n)  asm volatile("cp.async.wait_group %0;" :: "n"(n) : "memory")

#define LDSM4(R0,R1,R2,R3,ADDR) \
    asm volatile("ldmatrix.sync.aligned.m8n8.x4.shared.b16 {%0,%1,%2,%3}, [%4];" \
        : "=r"(R0), "=r"(R1), "=r"(R2), "=r"(R3) : "r"(ADDR))

static __device__ __forceinline__ void mmaf16(float (&d)[4], const uint32_t (&a)[4],
                                              uint32_t b0, uint32_t b1) {
    asm volatile(
        "mma.sync.aligned.m16n8k16.row.col.f32.f16.f16.f32 "
        "{%0,%1,%2,%3}, {%4,%5,%6,%7}, {%8,%9}, {%0,%1,%2,%3};"
        : "+f"(d[0]), "+f"(d[1]), "+f"(d[2]), "+f"(d[3])
        : "r"(a[0]), "r"(a[1]), "r"(a[2]), "r"(a[3]), "r"(b0), "r"(b1));
}

static __device__ __forceinline__ int lb(const int* __restrict__ a, int n, int v) {
    int lo = 0, hi = n;
    while (lo < hi) { int m = (lo + hi) >> 1; if (a[m] < v) lo = m + 1; else hi = m; }
    return lo;
}

// One 32x32 weight block vs this warp's 16-token A fragments.
// J = block-row position within the warp's half (compile-time -> static acc idx).
template<int J>
static __device__ __forceinline__ void do_block(float (&acc)[16][4],
                                                const uint32_t (&A)[2][4],
                                                uint32_t wb, int lane) {
    const int j = lane >> 3, r = lane & 7;
    const uint32_t base = wb + (uint32_t)(((j >> 1) * 8 + r) * 80 + (j & 1) * 16);
    #pragma unroll
    for (int p = 0; p < 2; p++) {
        #pragma unroll
        for (int ks = 0; ks < 2; ks++) {
            uint32_t b0, b1, b2, b3;
            LDSM4(b0, b1, b2, b3, base + (uint32_t)(p * 1280 + ks * 32));
            mmaf16(acc[J * 4 + p * 2 + 0], A[ks], b0, b1);
            mmaf16(acc[J * 4 + p * 2 + 1], A[ks], b2, b3);
        }
    }
}

// ---------------- pre-pass: fp32 -> fp16 ----------------
__global__ void cvt_f16_kernel(const float4* __restrict__ src, uint2* __restrict__ dst, int n4) {
    for (int i = blockIdx.x * blockDim.x + threadIdx.x; i < n4; i += gridDim.x * blockDim.x) {
        float4 v = src[i];
        __half2 h0 = __floats2half2_rn(v.x, v.y);
        __half2 h1 = __floats2half2_rn(v.z, v.w);
        uint2 o;
        o.x = *reinterpret_cast<uint32_t*>(&h0);
        o.y = *reinterpret_cast<uint32_t*>(&h1);
        dst[i] = o;
    }
}

// ---------------- main block-sparse GEMM ----------------
__global__ void __launch_bounds__(512, 1)
bsl_main(const float* __restrict__ bias,
         const int* __restrict__ block_ids,
         float* __restrict__ out)
{
    extern __shared__ __align__(1024) char smem[];
    const uint32_t sb = smem_u32(smem);
    const int tid  = threadIdx.x;
    const int wid  = tid >> 5;
    const int lane = tid & 31;
    const int wsub = wid & 7;         // token subtile (16 rows each)
    const int h    = wid >> 3;        // block-row half (4 block-rows = 128 cols)
    const int m0   = blockIdx.x * MT;
    const int brg  = blockIdx.y;      // 8-block-row group (0..15)

    int*      row_off = (int*)(smem + OFF_ROWOFF);
    int*      cnt     = (int*)(smem + OFF_CNT);
    uint32_t* ubc     = (uint32_t*)(smem + OFF_UBC);
    float*    bias_s  = (float*)(smem + OFF_BIAS);
    uint32_t* ents    = (uint32_t*)(smem + OFF_ENT);

    // ---- planning: CSR row offsets for our 8 block-rows ----
    if (tid < 9) row_off[tid] = lb(block_ids, N_BLK, (brg * NBR + tid) * IN_B);
    if (tid >= 32 && tid < 160) cnt[tid - 32] = 0;
    if (tid < GCOLS) bias_s[tid] = bias[brg * GCOLS + tid];
    __syncthreads();

    const int e0  = row_off[0];
    const int tot = row_off[NBR] - e0;

    for (int t = tid; t < tot; t += 512)
        atomicAdd(&cnt[block_ids[e0 + t] & 127], 1);
    __syncthreads();

    if (tid == 0) {
        int acc = 0, nuv = 0;
        for (int c = 0; c < 128; c++) {
            int cc = cnt[c];
            if (cc) ubc[nuv++] = ((uint32_t)c << 17) | ((uint32_t)acc << 5) | (uint32_t)cc;
            cnt[c] = acc; acc += cc;
        }
        *(int*)(smem + OFF_NU) = nuv;
    }
    __syncthreads();

    for (int t = tid; t < tot; t += 512) {
        int flat = block_ids[e0 + t];
        int bc   = flat & 127;
        int brl  = (flat >> 7) - brg * NBR;          // 0..7
        int pos  = atomicAdd(&cnt[bc], 1);
        ents[pos] = ((uint32_t)(e0 + t) << 8) | (uint32_t)brl;
    }
    __syncthreads();

    const int nu = *(int*)(smem + OFF_NU);

    // ---- loader (CTA-wide): x tile + weight blocks for one bc ----
    auto issue_loads = [&](int it, int stage) {
        uint32_t u = ubc[it];
        int bc = (int)(u >> 17);
        int st = (int)((u >> 5) & 0xFFF);
        int cc = (int)(u & 31);
        uint32_t xbase = sb + OFF_STG + (uint32_t)stage * STAGE;
        {   // 512 x-chunks of 16B, exactly one per thread
            int r = tid >> 2, c = tid & 3;
            cp16(xbase + (uint32_t)(r * 80 + c * 16),
                 g_xh + (size_t)(m0 + r) * IN_F + bc * 32 + c * 8);
        }
        uint32_t wbase = xbase + X_SZ;
        int totc = cc << 7;                          // 128 chunks per block
        for (int t = tid; t < totc; t += 512) {
            int e = t >> 7, o = t & 127, r = o >> 2, c = o & 3;
            uint32_t gg = ents[st + e] >> 8;
            cp16(wbase + (uint32_t)(e * WBLK + r * 80 + c * 16),
                 g_wh + (size_t)gg * 1024 + r * 32 + c * 8);
        }
        CP_COMMIT();
    };

    float acc[16][4];
    #pragma unroll
    for (int nt = 0; nt < 16; nt++)
        #pragma unroll
        for (int q = 0; q < 4; q++) acc[nt][q] = 0.0f;

    if (nu > 0) {
        issue_loads(0, 0);
        if (nu > 1) issue_loads(1, 1);

        for (int i = 0; i < nu; i++) {
            if (i + 1 < nu) CP_WAIT(1); else CP_WAIT(0);
            __syncthreads();
            if (i + 2 < nu) issue_loads(i + 2, (i + 2) % 3);

            int s = i % 3;
            uint32_t u = ubc[i];
            int st = (int)((u >> 5) & 0xFFF);
            int cc = (int)(u & 31);

            // does this warp's half have any block this iteration?
            bool any = false;
            #pragma unroll 4
            for (int e = 0; e < cc; e++)
                if ((int)((ents[st + e] >> 2) & 1) == h) { any = true; break; }

            if (any) {
                uint32_t xs = sb + OFF_STG + (uint32_t)s * STAGE;
                const int j = lane >> 3, rr = lane & 7;
                uint32_t xa = xs + (uint32_t)((wsub * 16 + (j & 1) * 8 + rr) * 80 + (j >> 1) * 16);
                uint32_t A[2][4];
                LDSM4(A[0][0], A[0][1], A[0][2], A[0][3], xa);
                LDSM4(A[1][0], A[1][1], A[1][2], A[1][3], xa + 32);

                uint32_t wb0 = xs + X_SZ;
                for (int e = 0; e < cc; e++) {
                    uint32_t en = ents[st + e];
                    int brl = (int)(en & 7);
                    if ((brl >> 2) != h) continue;
                    uint32_t wb = wb0 + (uint32_t)e * WBLK;
                    switch (brl & 3) {
                        case 0: do_block<0>(acc, A, wb, lane); break;
                        case 1: do_block<1>(acc, A, wb, lane); break;
                        case 2: do_block<2>(acc, A, wb, lane); break;
                        default: do_block<3>(acc, A, wb, lane); break;
                    }
                }
            }
        }
    }

    // ---- epilogue: registers -> gmem with bias ----
    {
        const int r4 = lane >> 2, c2 = (lane & 3) * 2;
        const int row = m0 + wsub * 16 + r4;
        const float* bs = bias_s + h * 128;
        #pragma unroll
        for (int nt = 0; nt < 16; nt++) {
            int lc = nt * 8 + c2;
            float b0 = bs[lc], b1 = bs[lc + 1];
            float* p = out + (size_t)row * OUT_F + brg * GCOLS + h * 128 + lc;
            float2 v0 = { acc[nt][0] + b0, acc[nt][1] + b1 };
            float2 v1 = { acc[nt][2] + b0, acc[nt][3] + b1 };
            *(float2*)p = v0;
            *(float2*)(p + 8 * OUT_F) = v1;
        }
    }
}

// ---------------- launch ----------------
extern "C" void kernel_launch(void* const* d_in, const int* in_sizes, int n_in,
                              void* d_out, int out_size)
{
    const float* x    = (const float*)d_in[0];   // [4096,4096] f32
    const float* w    = (const float*)d_in[1];   // [8192,32,32] f32
    const float* bias = (const float*)d_in[2];   // [4096] f32
    const int*   bids = (const int*)d_in[3];     // [8192] i32 sorted flat ids
    float* out = (float*)d_out;

    void* px = nullptr; void* pw = nullptr;
    cudaGetSymbolAddress(&px, g_xh);
    cudaGetSymbolAddress(&pw, g_wh);

    cvt_f16_kernel<<<4096, 256>>>((const float4*)x, (uint2*)px, (N_TOK * IN_F) / 4);
    cvt_f16_kernel<<<2048, 256>>>((const float4*)w, (uint2*)pw, (N_BLK * 1024) / 4);

    cudaFuncSetAttribute(bsl_main, cudaFuncAttributeMaxDynamicSharedMemorySize, SMEM_TOTAL);
    bsl_main<<<dim3(32, 16), 512, SMEM_TOTAL>>>(bias, bids, out);

    (void)in_sizes; (void)n_in; (void)out_size;
}

// round 4
// speedup vs baseline: 1.4381x; 1.0103x over previous
#include <cuda_runtime.h>
#include <cuda_fp16.h>
#include <cstdint>

// ---------------- problem constants ----------------
#define N_TOK 4096
#define IN_F  4096
#define OUT_F 4096
#define N_BLK 8192
#define IN_B  128          // IN_FEATURES / 32
#define NBR   8            // block-rows per CTA -> 256 output cols
#define GCOLS 256
#define MT    64           // token tile (64 rows -> 2 CTAs/SM)

// ---------------- smem layout (bytes) ----------------
#define OFF_NU     0
#define OFF_ROWOFF 32       // 9 ints
#define OFF_CNT    128      // 128 ints
#define OFF_UBC    640      // 128 u32
#define OFF_BIAS   1152     // 256 floats
#define OFF_ENT    2176     // up to 512 u32
#define OFF_STG    4352     // 3 pipeline stages
#define X_SZ       5120     // 64 rows * 80B (32 halves + 16B pad)
#define WBLK       2560     // 32 rows * 80B
#define STAGE      25600    // x + 8 weight blocks
#define SMEM_TOTAL (4352 + 3 * STAGE)   // 81152 -> 2 CTAs/SM fit

// fp16 copies of x and weights (alloc-free rule -> device globals)
__device__ __half g_xh[(size_t)N_TOK * IN_F];
__device__ __half g_wh[(size_t)N_BLK * 1024];

// ---------------- helpers ----------------
static __device__ __forceinline__ uint32_t smem_u32(const void* p) {
    uint32_t a;
    asm("{ .reg .u64 t; cvta.to.shared.u64 t, %1; cvt.u32.u64 %0, t; }" : "=r"(a) : "l"(p));
    return a;
}
static __device__ __forceinline__ void cp16(uint32_t dst, const void* src) {
    asm volatile("cp.async.cg.shared.global [%0], [%1], 16;" :: "r"(dst), "l"(src));
}
#define CP_COMMIT() asm volatile("cp.async.commit_group;" ::: "memory")
#define CP_WAIT(n)  asm volatile("cp.async.wait_group %0;" :: "n"(n) : "memory")

#define LDSM4(R0,R1,R2,R3,ADDR) \
    asm volatile("ldmatrix.sync.aligned.m8n8.x4.shared.b16 {%0,%1,%2,%3}, [%4];" \
        : "=r"(R0), "=r"(R1), "=r"(R2), "=r"(R3) : "r"(ADDR))

static __device__ __forceinline__ void mmaf16(float (&d)[4], const uint32_t (&a)[4],
                                              uint32_t b0, uint32_t b1) {
    asm volatile(
        "mma.sync.aligned.m16n8k16.row.col.f32.f16.f16.f32 "
        "{%0,%1,%2,%3}, {%4,%5,%6,%7}, {%8,%9}, {%0,%1,%2,%3};"
        : "+f"(d[0]), "+f"(d[1]), "+f"(d[2]), "+f"(d[3])
        : "r"(a[0]), "r"(a[1]), "r"(a[2]), "r"(a[3]), "r"(b0), "r"(b1));
}

static __device__ __forceinline__ int lb(const int* __restrict__ a, int n, int v) {
    int lo = 0, hi = n;
    while (lo < hi) { int m = (lo + hi) >> 1; if (a[m] < v) lo = m + 1; else hi = m; }
    return lo;
}

// One 32x32 weight block vs this warp's 16-token A fragments.
// J = block-row position within the warp's half (compile-time -> static acc idx).
template<int J>
static __device__ __forceinline__ void do_block(float (&acc)[16][4],
                                                const uint32_t (&A)[2][4],
                                                uint32_t wb, int lane) {
    const int j = lane >> 3, r = lane & 7;
    const uint32_t base = wb + (uint32_t)(((j >> 1) * 8 + r) * 80 + (j & 1) * 16);
    #pragma unroll
    for (int p = 0; p < 2; p++) {
        #pragma unroll
        for (int ks = 0; ks < 2; ks++) {
            uint32_t b0, b1, b2, b3;
            LDSM4(b0, b1, b2, b3, base + (uint32_t)(p * 1280 + ks * 32));
            mmaf16(acc[J * 4 + p * 2 + 0], A[ks], b0, b1);
            mmaf16(acc[J * 4 + p * 2 + 1], A[ks], b2, b3);
        }
    }
}

// ---------------- pre-pass: fp32 -> fp16 ----------------
__global__ void cvt_f16_kernel(const float4* __restrict__ src, uint2* __restrict__ dst, int n4) {
    for (int i = blockIdx.x * blockDim.x + threadIdx.x; i < n4; i += gridDim.x * blockDim.x) {
        float4 v = src[i];
        __half2 h0 = __floats2half2_rn(v.x, v.y);
        __half2 h1 = __floats2half2_rn(v.z, v.w);
        uint2 o;
        o.x = *reinterpret_cast<uint32_t*>(&h0);
        o.y = *reinterpret_cast<uint32_t*>(&h1);
        dst[i] = o;
    }
}

// ---------------- main block-sparse GEMM ----------------
__global__ void __launch_bounds__(256, 2)
bsl_main(const float* __restrict__ bias,
         const int* __restrict__ block_ids,
         float* __restrict__ out)
{
    extern __shared__ __align__(1024) char smem[];
    const uint32_t sb = smem_u32(smem);
    const int tid  = threadIdx.x;
    const int wid  = tid >> 5;
    const int lane = tid & 31;
    const int wsub = wid & 3;         // token subtile (16 rows each)
    const int h    = wid >> 2;        // block-row half (4 block-rows = 128 cols)
    const int m0   = blockIdx.x * MT;
    const int brg  = blockIdx.y;      // 8-block-row group (0..15)

    int*      row_off = (int*)(smem + OFF_ROWOFF);
    int*      cnt     = (int*)(smem + OFF_CNT);
    uint32_t* ubc     = (uint32_t*)(smem + OFF_UBC);
    float*    bias_s  = (float*)(smem + OFF_BIAS);
    uint32_t* ents    = (uint32_t*)(smem + OFF_ENT);

    // ---- planning: CSR row offsets for our 8 block-rows ----
    if (tid < 9) row_off[tid] = lb(block_ids, N_BLK, (brg * NBR + tid) * IN_B);
    if (tid >= 32 && tid < 160) cnt[tid - 32] = 0;
    if (tid < GCOLS) bias_s[tid] = bias[brg * GCOLS + tid];
    __syncthreads();

    const int e0  = row_off[0];
    const int tot = row_off[NBR] - e0;

    for (int t = tid; t < tot; t += 256)
        atomicAdd(&cnt[block_ids[e0 + t] & 127], 1);
    __syncthreads();

    if (tid == 0) {
        int acc = 0, nuv = 0;
        for (int c = 0; c < 128; c++) {
            int cc = cnt[c];
            if (cc) ubc[nuv++] = ((uint32_t)c << 17) | ((uint32_t)acc << 5) | (uint32_t)cc;
            cnt[c] = acc; acc += cc;
        }
        *(int*)(smem + OFF_NU) = nuv;
    }
    __syncthreads();

    for (int t = tid; t < tot; t += 256) {
        int flat = block_ids[e0 + t];
        int bc   = flat & 127;
        int brl  = (flat >> 7) - brg * NBR;          // 0..7
        int pos  = atomicAdd(&cnt[bc], 1);
        ents[pos] = ((uint32_t)(e0 + t) << 8) | (uint32_t)brl;
    }
    __syncthreads();

    const int nu = *(int*)(smem + OFF_NU);

    // ---- loader (CTA-wide): x tile + weight blocks for one bc ----
    auto issue_loads = [&](int it, int stage) {
        uint32_t u = ubc[it];
        int bc = (int)(u >> 17);
        int st = (int)((u >> 5) & 0xFFF);
        int cc = (int)(u & 31);
        uint32_t xbase = sb + OFF_STG + (uint32_t)stage * STAGE;
        {   // 256 x-chunks of 16B, exactly one per thread
            int r = tid >> 2, c = tid & 3;
            cp16(xbase + (uint32_t)(r * 80 + c * 16),
                 g_xh + (size_t)(m0 + r) * IN_F + bc * 32 + c * 8);
        }
        uint32_t wbase = xbase + X_SZ;
        int totc = cc << 7;                          // 128 chunks per block
        #pragma unroll
        for (int q = 0; q < 4; q++) {
            int t = tid + q * 256;
            if (t < totc) {
                int e = t >> 7, o = t & 127, r = o >> 2, c = o & 3;
                uint32_t gg = ents[st + e] >> 8;
                cp16(wbase + (uint32_t)(e * WBLK + r * 80 + c * 16),
                     g_wh + (size_t)gg * 1024 + r * 32 + c * 8);
            }
        }
        CP_COMMIT();
    };

    float acc[16][4];
    #pragma unroll
    for (int nt = 0; nt < 16; nt++)
        #pragma unroll
        for (int q = 0; q < 4; q++) acc[nt][q] = 0.0f;

    if (nu > 0) {
        issue_loads(0, 0);
        if (nu > 1) issue_loads(1, 1);

        for (int i = 0; i < nu; i++) {
            if (i + 1 < nu) CP_WAIT(1); else CP_WAIT(0);
            __syncthreads();
            if (i + 2 < nu) issue_loads(i + 2, (i + 2) % 3);

            int s = i % 3;
            uint32_t u = ubc[i];
            int st = (int)((u >> 5) & 0xFFF);
            int cc = (int)(u & 31);

            // does this warp's half have any block this iteration?
            bool any = false;
            #pragma unroll 4
            for (int e = 0; e < cc; e++)
                if ((int)((ents[st + e] >> 2) & 1) == h) { any = true; break; }

            if (any) {
                uint32_t xs = sb + OFF_STG + (uint32_t)s * STAGE;
                const int j = lane >> 3, rr = lane & 7;
                uint32_t xa = xs + (uint32_t)((wsub * 16 + (j & 1) * 8 + rr) * 80 + (j >> 1) * 16);
                uint32_t A[2][4];
                LDSM4(A[0][0], A[0][1], A[0][2], A[0][3], xa);
                LDSM4(A[1][0], A[1][1], A[1][2], A[1][3], xa + 32);

                uint32_t wb0 = xs + X_SZ;
                for (int e = 0; e < cc; e++) {
                    uint32_t en = ents[st + e];
                    int brl = (int)(en & 7);
                    if ((brl >> 2) != h) continue;
                    uint32_t wb = wb0 + (uint32_t)e * WBLK;
                    switch (brl & 3) {
                        case 0: do_block<0>(acc, A, wb, lane); break;
                        case 1: do_block<1>(acc, A, wb, lane); break;
                        case 2: do_block<2>(acc, A, wb, lane); break;
                        default: do_block<3>(acc, A, wb, lane); break;
                    }
                }
            }
        }
    }

    // ---- epilogue: registers -> gmem with bias ----
    {
        const int r4 = lane >> 2, c2 = (lane & 3) * 2;
        const int row = m0 + wsub * 16 + r4;
        const float* bs = bias_s + h * 128;
        #pragma unroll
        for (int nt = 0; nt < 16; nt++) {
            int lc = nt * 8 + c2;
            float b0 = bs[lc], b1 = bs[lc + 1];
            float* p = out + (size_t)row * OUT_F + brg * GCOLS + h * 128 + lc;
            float2 v0 = { acc[nt][0] + b0, acc[nt][1] + b1 };
            float2 v1 = { acc[nt][2] + b0, acc[nt][3] + b1 };
            *(float2*)p = v0;
            *(float2*)(p + 8 * OUT_F) = v1;
        }
    }
}

// ---------------- launch ----------------
extern "C" void kernel_launch(void* const* d_in, const int* in_sizes, int n_in,
                              void* d_out, int out_size)
{
    const float* x    = (const float*)d_in[0];   // [4096,4096] f32
    const float* w    = (const float*)d_in[1];   // [8192,32,32] f32
    const float* bias = (const float*)d_in[2];   // [4096] f32
    const int*   bids = (const int*)d_in[3];     // [8192] i32 sorted flat ids
    float* out = (float*)d_out;

    void* px = nullptr; void* pw = nullptr;
    cudaGetSymbolAddress(&px, g_xh);
    cudaGetSymbolAddress(&pw, g_wh);

    cvt_f16_kernel<<<4096, 256>>>((const float4*)x, (uint2*)px, (N_TOK * IN_F) / 4);
    cvt_f16_kernel<<<2048, 256>>>((const float4*)w, (uint2*)pw, (N_BLK * 1024) / 4);

    cudaFuncSetAttribute(bsl_main, cudaFuncAttributeMaxDynamicSharedMemorySize, SMEM_TOTAL);
    bsl_main<<<dim3(64, 16), 256, SMEM_TOTAL>>>(bias, bids, out);

    (void)in_sizes; (void)n_in; (void)out_size;
}